// round 17
// baseline (speedup 1.0000x reference)
#include <cuda_runtime.h>
#include <cuda_fp16.h>

typedef unsigned long long ull;
typedef unsigned int u32;

#define NEG 0.2f
#define LNEPS 1e-5f
#define L2E 1.44269504f

// A/B fp16 tiles, K=80 augmented (64 x | 7 ea | 9 zero), row stride 88 elems
#define KA 88
// dynamic smem byte offsets
#define T_AH  0                     // fp16 [128][88] = 22528 B
#define T_B   22528                 // fp16 B [256][88] = 45056 B
#define O_XR  67584                 // f32 [2][256]
#define O_ATT 69632                 // f32 [256]
#define O_LG  70656                 // f32 [128][4]
#define O_ZP  72704                 // f32 partials (8KB; also input scratch)
#define O_Z   80896                 // f32 [8][64]
#define O_O4  82944                 // f32 [2pl][4h][64]
#define O_XP  84992                 // f32 [128]
#define O_RED 85504                 // f32 [8]
#define DSMEM_BYTES 85536

__device__ __half g_B[2][256 * KA];
__device__ float g_XR0[4096 * 256];   // layer-0 xr + br + bl (exact hoist)

__device__ __forceinline__ u32 smem_u32(const void* p) {
    u32 a; asm("{ .reg .u64 t; cvta.to.shared.u64 t, %1; cvt.u32.u64 %0, t; }"
               : "=r"(a) : "l"(p));
    return a;
}
__device__ __forceinline__ float ex2(float x) {
    float r; asm("ex2.approx.f32 %0, %1;" : "=f"(r) : "f"(x)); return r;
}
__device__ __forceinline__ ull pack2(float lo, float hi) {
    ull r; asm("mov.b64 %0, {%1, %2};" : "=l"(r) : "f"(lo), "f"(hi)); return r;
}
__device__ __forceinline__ void unpack2(ull v, float& lo, float& hi) {
    asm("mov.b64 {%0, %1}, %2;" : "=f"(lo), "=f"(hi) : "l"(v));
}
__device__ __forceinline__ ull ffma2(ull a, ull b, ull c) {
    ull d; asm("fma.rn.f32x2 %0, %1, %2, %3;" : "=l"(d) : "l"(a), "l"(b), "l"(c));
    return d;
}
__device__ __forceinline__ void ldsm4(u32& r0, u32& r1, u32& r2, u32& r3, u32 a) {
    asm volatile("ldmatrix.sync.aligned.m8n8.x4.shared.b16 {%0,%1,%2,%3}, [%4];"
                 : "=r"(r0), "=r"(r1), "=r"(r2), "=r"(r3) : "r"(a));
}
__device__ __forceinline__ void mma_f16(float* d, const u32* a, u32 b0, u32 b1) {
    asm volatile("mma.sync.aligned.m16n8k16.row.col.f32.f16.f16.f32 "
                 "{%0,%1,%2,%3}, {%4,%5,%6,%7}, {%8,%9}, {%0,%1,%2,%3};"
                 : "+f"(d[0]), "+f"(d[1]), "+f"(d[2]), "+f"(d[3])
                 : "r"(a[0]), "r"(a[1]), "r"(a[2]), "r"(a[3]),
                   "r"(b0), "r"(b1));
}
__device__ __forceinline__ u32 h2pack(float a0, float a1) {
    __half2 h = __floats2half2_rn(a0, a1);
    return *(u32*)&h;
}
__device__ __forceinline__ void cpasync16(u32 saddr, const void* g) {
    asm volatile("cp.async.cg.shared.global [%0], [%1], 16;"
                 :: "r"(saddr), "l"(g) : "memory");
}

// merged prep: blocks 0..175 convert B; blocks 176..303 compute layer-0 xr
__global__ void __launch_bounds__(256) prep_all(
    const float* __restrict__ Wl, const float* __restrict__ We,
    const float* __restrict__ player_feat,
    const float* __restrict__ Wp, const float* __restrict__ bp,
    const float* __restrict__ Wr, const float* __restrict__ br,
    const float* __restrict__ bl)
{
    extern __shared__ float sWr[];       // 64KB (xr blocks only)
    const int t = threadIdx.x;

    if (blockIdx.x < 176) {
        int i = blockIdx.x * 256 + t;    // 2*256*88 = 45056
        int l = i / (256 * KA), r = i % (256 * KA);
        int n = r / KA, k = r % KA;
        float w = 0.f;
        if (k < 64)      w = Wl[l * 16384 + k * 256 + n];
        else if (k < 71) w = We[l * 1792 + (k - 64) * 256 + n];
        g_B[l][n * KA + k] = __float2half_rn(w);
        return;
    }

    __shared__ float s_xp[32 * 64];
    const int pbase = (blockIdx.x - 176) * 32;

    #pragma unroll
    for (int idx = t; idx < 2048; idx += 256) {
        int p = idx >> 6, k = idx & 63;
        float acc = bp[k];
        #pragma unroll
        for (int j = 0; j < 5; j++)
            acc += player_feat[(pbase + p) * 5 + j] * Wp[j * 64 + k];
        s_xp[idx] = fmaxf(acc, 0.f);
    }
    const float4* Wg = (const float4*)Wr;    // layer 0
    #pragma unroll
    for (int i = t; i < 4096; i += 256)
        ((float4*)sWr)[i] = Wg[i];
    __syncthreads();

    const int c = t;
    float bsum = br[c] + bl[c];
    float acc[32];
    #pragma unroll
    for (int p = 0; p < 32; p++) acc[p] = bsum;
    #pragma unroll 4
    for (int k = 0; k < 64; k++) {
        float w = sWr[k * 256 + c];
        #pragma unroll
        for (int p = 0; p < 32; p++)
            acc[p] = fmaf(s_xp[p * 64 + k], w, acc[p]);
    }
    #pragma unroll
    for (int p = 0; p < 32; p++)
        g_XR0[(pbase + p) * 256 + c] = acc[p];
}

__global__ void __launch_bounds__(256, 2)
gnn_tc_kernel(const float* __restrict__ player_feat,
              const float* __restrict__ asteroid_feat,
              const float* __restrict__ edge_attr,
              const float* __restrict__ Wp, const float* __restrict__ bp,
              const float* __restrict__ Wa, const float* __restrict__ ba,
              const float* __restrict__ bl,
              const float* __restrict__ Wr, const float* __restrict__ br,
              const float* __restrict__ att,
              const float* __restrict__ bias, const float* __restrict__ ln_g,
              const float* __restrict__ ln_b,
              float* __restrict__ out)
{
    extern __shared__ char dsm[];
    const u32 S = smem_u32(dsm);
    float* s_xr  = (float*)(dsm + O_XR);
    float* s_att = (float*)(dsm + O_ATT);
    float* s_lg  = (float*)(dsm + O_LG);
    float* s_zp  = (float*)(dsm + O_ZP);
    float* s_z   = (float*)(dsm + O_Z);
    float* s_o4  = (float*)(dsm + O_O4);
    float* s_xp  = (float*)(dsm + O_XP);
    float* s_red = (float*)(dsm + O_RED);

    const int bid  = blockIdx.x;             // players 2*bid, 2*bid+1
    const int t    = threadIdx.x;
    const int warp = t >> 5;
    const int lane = t & 31;

    // issue B[0] staging immediately (cp.async.cg: bypasses L1, no STS)
    {
        const uint4* sb = (const uint4*)g_B[0];
        u32 db = S + T_B + t * 16;
        #pragma unroll
        for (int i = 0; i < 11; i++)
            cpasync16(db + i * 4096, sb + t + i * 256);
        asm volatile("cp.async.commit_group;" ::: "memory");
    }

    // ---- stage inputs via coalesced float4 into scratch (s_zp area) ----
    float* scr = s_zp;                        // [0..384) feats, [384..1280) ea
    if (t < 96)
        ((float4*)scr)[t] = ((const float4*)(asteroid_feat + (long)bid * 384))[t];
    if (t < 224)
        ((float4*)(scr + 384))[t] = ((const float4*)(edge_attr + (long)bid * 896))[t];
    if (t < 128) {
        int pl = t >> 6, o = t & 63;
        float acc = bp[o];
        #pragma unroll
        for (int k = 0; k < 5; k++)
            acc += player_feat[(bid * 2 + pl) * 5 + k] * Wp[k * 64 + o];
        s_xp[t] = fmaxf(acc, 0.f);
    }
    __syncthreads();

    // ---- A-tile build: register-packed, rotated uint4 stores ----
    {
        int a = t >> 1, hf = t & 1;          // 32 k-cols per thread
        float f0 = scr[a * 3 + 0];
        float f1 = scr[a * 3 + 1];
        float f2 = scr[a * 3 + 2];
        u32 hx[16];
        #pragma unroll
        for (int q = 0; q < 16; q++) {
            int o0 = hf * 32 + 2 * q;
            float v0 = fmaxf(ba[o0]     + f0 * Wa[o0]     + f1 * Wa[64 + o0]
                                        + f2 * Wa[128 + o0], 0.f);
            float v1 = fmaxf(ba[o0 + 1] + f0 * Wa[o0 + 1] + f1 * Wa[64 + o0 + 1]
                                        + f2 * Wa[128 + o0 + 1], 0.f);
            hx[q] = h2pack(v0, v1);
        }
        uint4* AH4 = (uint4*)(dsm + T_AH + a * KA * 2 + hf * 64);
        #pragma unroll
        for (int g = 0; g < 4; g++) {
            int gg = (g + a) & 3;            // bank-conflict rotation
            AH4[gg] = make_uint4(hx[gg*4], hx[gg*4+1], hx[gg*4+2], hx[gg*4+3]);
        }
    }
    if (t < 128) {                 // ea cols 64..70 + zero pad, 3 uint4
        const float* eap = scr + 384 + t * 7;
        u32 w[6] = {0, 0, 0, 0, 0, 0};
        #pragma unroll
        for (int k = 0; k < 7; k++) {
            float v = eap[k];
            w[k >> 1] |= (u32)__half_as_ushort(__float2half_rn(v)) << ((k & 1) * 16);
        }
        uint4* AH4 = (uint4*)(dsm + T_AH + t * KA * 2 + 128);
        AH4[0] = make_uint4(w[0], w[1], w[2], w[3]);
        AH4[1] = make_uint4(w[4], w[5], 0u, 0u);
        AH4[2] = make_uint4(0u, 0u, 0u, 0u);
    }
    __syncthreads();

    // warp tile: rows rb*32..+31, heads 2*hp..2*hp+1
    const int rb = warp >> 1;                 // row block 0..3
    const int hp = warp & 1;                  // head pair
    const int pl_w = rb >> 1;                 // player of these rows
    const u32 aoff0 = (u32)(((rb * 32 + (lane & 15)) * KA + ((lane >> 4) << 3)) * 2);
    const u32 aoff1 = aoff0 + (u32)(16 * KA * 2);
    const u32 boff = (u32)((((lane & 7) + ((lane & 16) >> 1)) * KA) * 2
                           + (((lane >> 3) & 1) << 4));

    #pragma unroll 1
    for (int l = 0; l < 2; l++) {
        // ---- xr: layer 0 precomputed (exact); layer 1 in-kernel ----
        if (l == 0) {
            if (t < 128)
                ((float4*)s_xr)[t] =
                    ((const float4*)(g_XR0 + (long)bid * 512))[t];
        } else {
            int c = t;
            float base = br[256 + c] + bl[256 + c];
            float x0a = 0.f, x0b = 0.f, x1a = 0.f, x1b = 0.f;
            const float* Wrl = Wr + 16384 + c;
            #pragma unroll 4
            for (int k = 0; k < 64; k += 2) {
                float w0 = __ldg(Wrl + k * 256);
                float w1 = __ldg(Wrl + (k + 1) * 256);
                x0a = fmaf(w0, s_xp[k],      x0a);
                x0b = fmaf(w1, s_xp[k + 1],  x0b);
                x1a = fmaf(w0, s_xp[64 + k], x1a);
                x1b = fmaf(w1, s_xp[64 + k + 1], x1b);
            }
            s_xr[c]       = base + x0a + x0b;
            s_xr[256 + c] = base + x1a + x1b;
        }
        s_att[t] = att[l * 256 + t];
        asm volatile("cp.async.wait_group 0;" ::: "memory");
        __syncthreads();

        // ---- A fragments for 32 rows, once per layer ----
        u32 A0[5][4], A1[5][4];
        #pragma unroll
        for (int ks = 0; ks < 5; ks++) {
            ldsm4(A0[ks][0], A0[ks][1], A0[ks][2], A0[ks][3],
                  S + T_AH + aoff0 + ks * 32);
            ldsm4(A1[ks][0], A1[ks][1], A1[ks][2], A1[ks][3],
                  S + T_AH + aoff1 + ks * 32);
        }

        // ---- GEMM + logits: 2 heads, each in two 32-col halves ----
        #pragma unroll 1
        for (int hh = 0; hh < 2; hh++) {
            int h = hp * 2 + hh;
            float lgA0 = 0.f, lgB0 = 0.f;
            float lgA1 = 0.f, lgB1 = 0.f;
            #pragma unroll 1
            for (int nh = 0; nh < 2; nh++) {
                float acc[8][4];
                #pragma unroll
                for (int i = 0; i < 8; i++)
                    #pragma unroll
                    for (int j = 0; j < 4; j++) acc[i][j] = 0.f;

                u32 bbase = S + T_B + boff
                          + (u32)((h * 64 + nh * 32) * KA * 2);
                #pragma unroll
                for (int ks = 0; ks < 5; ks++) {
                    #pragma unroll
                    for (int ntp = 0; ntp < 2; ntp++) {
                        u32 b0, b1, b2, b3;
                        ldsm4(b0, b1, b2, b3,
                              bbase + (u32)(ntp * 16 * KA * 2) + ks * 32);
                        mma_f16(acc[ntp * 2],     A0[ks], b0, b1);
                        mma_f16(acc[ntp * 2 + 1], A0[ks], b2, b3);
                        mma_f16(acc[4 + ntp * 2],     A1[ks], b0, b1);
                        mma_f16(acc[4 + ntp * 2 + 1], A1[ks], b2, b3);
                    }
                }
                #pragma unroll
                for (int ct = 0; ct < 4; ct++) {
                    int c = h * 64 + nh * 32 + ct * 8 + (lane & 3) * 2;
                    float2 xr = *(const float2*)(s_xr + pl_w * 256 + c);
                    float2 at = *(const float2*)(s_att + c);
                    float v0, v1;
                    v0 = acc[ct][0] + xr.x; v1 = acc[ct][1] + xr.y;
                    v0 = fmaxf(v0, NEG * v0); v1 = fmaxf(v1, NEG * v1);
                    lgA0 = fmaf(v0, at.x, fmaf(v1, at.y, lgA0));
                    v0 = acc[ct][2] + xr.x; v1 = acc[ct][3] + xr.y;
                    v0 = fmaxf(v0, NEG * v0); v1 = fmaxf(v1, NEG * v1);
                    lgB0 = fmaf(v0, at.x, fmaf(v1, at.y, lgB0));
                    v0 = acc[4 + ct][0] + xr.x; v1 = acc[4 + ct][1] + xr.y;
                    v0 = fmaxf(v0, NEG * v0); v1 = fmaxf(v1, NEG * v1);
                    lgA1 = fmaf(v0, at.x, fmaf(v1, at.y, lgA1));
                    v0 = acc[4 + ct][2] + xr.x; v1 = acc[4 + ct][3] + xr.y;
                    v0 = fmaxf(v0, NEG * v0); v1 = fmaxf(v1, NEG * v1);
                    lgB1 = fmaf(v0, at.x, fmaf(v1, at.y, lgB1));
                }
            }
            lgA0 += __shfl_xor_sync(0xffffffffu, lgA0, 1);
            lgB0 += __shfl_xor_sync(0xffffffffu, lgB0, 1);
            lgA1 += __shfl_xor_sync(0xffffffffu, lgA1, 1);
            lgB1 += __shfl_xor_sync(0xffffffffu, lgB1, 1);
            lgA0 += __shfl_xor_sync(0xffffffffu, lgA0, 2);
            lgB0 += __shfl_xor_sync(0xffffffffu, lgB0, 2);
            lgA1 += __shfl_xor_sync(0xffffffffu, lgA1, 2);
            lgB1 += __shfl_xor_sync(0xffffffffu, lgB1, 2);
            if ((lane & 3) == 0) {
                int r0 = rb * 32 + (lane >> 2);
                s_lg[r0 * 4 + h]        = lgA0;
                s_lg[(r0 + 8) * 4 + h]  = lgB0;
                s_lg[(r0 + 16) * 4 + h] = lgA1;
                s_lg[(r0 + 24) * 4 + h] = lgB1;
            }
        }
        __syncthreads();

        // ---- softmax: warp w -> (player w>>2, head w&3) ----
        {
            int pl = warp >> 2, h = warp & 3;
            int ra = pl * 64 + lane * 2;
            float v0 = s_lg[ra * 4 + h], v1 = s_lg[(ra + 1) * 4 + h];
            float m = fmaxf(v0, v1);
            #pragma unroll
            for (int s = 1; s < 32; s <<= 1)
                m = fmaxf(m, __shfl_xor_sync(0xffffffffu, m, s));
            float e0 = ex2((v0 - m) * L2E), e1 = ex2((v1 - m) * L2E);
            float den = e0 + e1;
            #pragma unroll
            for (int s = 1; s < 32; s <<= 1)
                den += __shfl_xor_sync(0xffffffffu, den, s);
            float inv = 1.f / den;
            s_lg[ra * 4 + h] = e0 * inv;
            s_lg[(ra + 1) * 4 + h] = e1 * inv;
        }
        __syncthreads();

        // ---- z partials: warp = (pl, rowgroup of 16), all 4 heads ----
        {
            int pl = warp >> 2, rg = warp & 3;
            int k0 = lane * 2;
            ull z2[4] = {0ull, 0ull, 0ull, 0ull};
            #pragma unroll 4
            for (int i = 0; i < 16; i++) {
                int row = pl * 64 + rg * 16 + i;
                u32 xh = *(const u32*)(dsm + T_AH + row * KA * 2 + k0 * 2);
                float2 fh = __half22float2(*(const __half2*)&xh);
                ull x2 = pack2(fh.x, fh.y);
                float4 al4 = *(const float4*)(s_lg + row * 4);
                z2[0] = ffma2(pack2(al4.x, al4.x), x2, z2[0]);
                z2[1] = ffma2(pack2(al4.y, al4.y), x2, z2[1]);
                z2[2] = ffma2(pack2(al4.z, al4.z), x2, z2[2]);
                z2[3] = ffma2(pack2(al4.w, al4.w), x2, z2[3]);
            }
            #pragma unroll
            for (int h = 0; h < 4; h++) {
                float a0, a1;
                unpack2(z2[h], a0, a1);
                *(float2*)(s_zp + ((pl * 4 + rg) * 4 + h) * 64 + k0) =
                    make_float2(a0, a1);
            }
        }
        __syncthreads();
        // reduce 4 rowgroup partials -> s_z[(pl*4+h)][k]
        {
            int pl = t >> 7, h = (t >> 5) & 3, k0 = (t & 31) * 2;
            float2 acc = make_float2(0.f, 0.f);
            #pragma unroll
            for (int rg = 0; rg < 4; rg++) {
                float2 v = *(const float2*)(s_zp + ((pl * 4 + rg) * 4 + h) * 64 + k0);
                acc.x += v.x; acc.y += v.y;
            }
            *(float2*)(s_z + (pl * 4 + h) * 64 + k0) = acc;
        }
        __syncthreads();

        // ---- out: thread = (h, o); B rows read with rotated q-slots ----
        {
            int h = t >> 6, o = t & 63;
            const uint4* Bw = (const uint4*)(dsm + T_B + (h * 64 + o) * KA * 2);
            const float* z0p = s_z + h * 64;
            const float* z1p = s_z + (4 + h) * 64;
            float a0 = 0.f, b0 = 0.f;
            #pragma unroll
            for (int q = 0; q < 8; q++) {
                int qq = (q + o) & 7;            // bank-conflict rotation
                uint4 w4 = Bw[qq];
                float2 w01 = __half22float2(*(const __half2*)&w4.x);
                float2 w23 = __half22float2(*(const __half2*)&w4.y);
                float2 w45 = __half22float2(*(const __half2*)&w4.z);
                float2 w67 = __half22float2(*(const __half2*)&w4.w);
                float4 za0 = *(const float4*)(z0p + qq * 8);
                float4 za1 = *(const float4*)(z0p + qq * 8 + 4);
                float4 zb0 = *(const float4*)(z1p + qq * 8);
                float4 zb1 = *(const float4*)(z1p + qq * 8 + 4);
                a0 = fmaf(w01.x, za0.x, fmaf(w01.y, za0.y, a0));
                a0 = fmaf(w23.x, za0.z, fmaf(w23.y, za0.w, a0));
                a0 = fmaf(w45.x, za1.x, fmaf(w45.y, za1.y, a0));
                a0 = fmaf(w67.x, za1.z, fmaf(w67.y, za1.w, a0));
                b0 = fmaf(w01.x, zb0.x, fmaf(w01.y, zb0.y, b0));
                b0 = fmaf(w23.x, zb0.z, fmaf(w23.y, zb0.w, b0));
                b0 = fmaf(w45.x, zb1.x, fmaf(w45.y, zb1.y, b0));
                b0 = fmaf(w67.x, zb1.z, fmaf(w67.y, zb1.w, b0));
            }
            float blv = bl[l * 256 + h * 64 + o];
            s_o4[h * 64 + o]       = a0 + blv;
            s_o4[256 + h * 64 + o] = b0 + blv;
        }
        __syncthreads();

        // kick B[1] staging AFTER the out phase finished reading s_B.
        if (l == 0) {
            const uint4* sb = (const uint4*)g_B[1];
            u32 db = S + T_B + t * 16;
            #pragma unroll
            for (int i = 0; i < 11; i++)
                cpasync16(db + i * 4096, sb + t + i * 256);
            asm volatile("cp.async.commit_group;" ::: "memory");
        }

        // ---- player update + LN (warps 0-3 only, named barrier) ----
        if (warp < 4) {
            int pl = t >> 6, o = t & 63;
            const float* op = s_o4 + pl * 256;
            float mean = 0.25f * (op[o] + op[64 + o] + op[128 + o] + op[192 + o])
                       + bias[l * 64 + o];
            float y = s_xp[t] + fmaxf(mean, 0.f);
            float s1 = y, s2 = y * y;
            #pragma unroll
            for (int s = 1; s < 32; s <<= 1) {
                s1 += __shfl_xor_sync(0xffffffffu, s1, s);
                s2 += __shfl_xor_sync(0xffffffffu, s2, s);
            }
            if (lane == 0) {
                s_red[warp * 2] = s1;
                s_red[warp * 2 + 1] = s2;
            }
            asm volatile("bar.sync 1, 128;" ::: "memory");
            float mu = (s_red[pl * 4] + s_red[pl * 4 + 2]) * (1.f / 64.f);
            float ms = (s_red[pl * 4 + 1] + s_red[pl * 4 + 3]) * (1.f / 64.f);
            float rstd = rsqrtf(ms - mu * mu + LNEPS);
            s_xp[t] = (y - mu) * rstd * ln_g[l * 64 + o] + ln_b[l * 64 + o];
        }

        // ---- asteroid update (feeds layer 1 only): fp16-hi state ----
        if (l == 0) {
            int a = t >> 1, hf = t & 1;
            uint4* AH4 = (uint4*)(dsm + T_AH + a * KA * 2 + hf * 64);
            uint4 H[4];
            #pragma unroll
            for (int g = 0; g < 4; g++) {
                int gg = (g + a) & 3;
                H[gg] = AH4[gg];
            }
            float v[32];
            float s1 = 0.f, s2 = 0.f;
            #pragma unroll
            for (int g = 0; g < 4; g++) {
                const u32* hw = (const u32*)&H[g];
                #pragma unroll
                for (int j = 0; j < 4; j++) {
                    float2 fh = __half22float2(*(const __half2*)&hw[j]);
                    int idx = g * 8 + j * 2;
                    int o0 = hf * 32 + idx;
                    float w0 = fh.x + fmaxf(bias[o0], 0.f);
                    float w1 = fh.y + fmaxf(bias[o0 + 1], 0.f);
                    v[idx] = w0; v[idx + 1] = w1;
                    s1 += w0 + w1;
                    s2 += w0 * w0 + w1 * w1;
                }
            }
            s1 += __shfl_xor_sync(0xffffffffu, s1, 1);
            s2 += __shfl_xor_sync(0xffffffffu, s2, 1);
            float mu = s1 * (1.f / 64.f);
            float rstd = rsqrtf(s2 * (1.f / 64.f) - mu * mu + LNEPS);
            #pragma unroll
            for (int g = 0; g < 4; g++) {
                int gg = (g + a) & 3;
                u32* hw = (u32*)&H[gg];
                #pragma unroll
                for (int j = 0; j < 4; j++) {
                    int idx = gg * 8 + j * 2;
                    int o0 = hf * 32 + idx;
                    float v0 = (v[idx]     - mu) * rstd * ln_g[o0]     + ln_b[o0];
                    float v1 = (v[idx + 1] - mu) * rstd * ln_g[o0 + 1] + ln_b[o0 + 1];
                    hw[j] = h2pack(v0, v1);
                }
                AH4[gg] = H[gg];
            }
        }
        __syncthreads();
    }

    if (t < 128) out[bid * 128 + t] = s_xp[t];
}

extern "C" void kernel_launch(void* const* d_in, const int* in_sizes, int n_in,
                              void* d_out, int out_size) {
    (void)in_sizes; (void)n_in; (void)out_size;
    cudaFuncSetAttribute(gnn_tc_kernel,
                         cudaFuncAttributeMaxDynamicSharedMemorySize, DSMEM_BYTES);
    cudaFuncSetAttribute(prep_all,
                         cudaFuncAttributeMaxDynamicSharedMemorySize, 65536);
    prep_all<<<304, 256, 65536>>>(
        (const float*)d_in[8],   // Wl
        (const float*)d_in[12],  // We
        (const float*)d_in[0],   // player_feat
        (const float*)d_in[4],   // Wp
        (const float*)d_in[5],   // bp
        (const float*)d_in[10],  // Wr
        (const float*)d_in[11],  // br
        (const float*)d_in[9]);  // bl
    gnn_tc_kernel<<<2048, 256, DSMEM_BYTES>>>(
        (const float*)d_in[0],   // player_feat
        (const float*)d_in[1],   // asteroid_feat
        (const float*)d_in[3],   // edge_attr
        (const float*)d_in[4],   // Wp
        (const float*)d_in[5],   // bp
        (const float*)d_in[6],   // Wa
        (const float*)d_in[7],   // ba
        (const float*)d_in[9],   // bl
        (const float*)d_in[10],  // Wr
        (const float*)d_in[11],  // br
        (const float*)d_in[13],  // att
        (const float*)d_in[14],  // bias
        (const float*)d_in[15],  // ln_g
        (const float*)d_in[16],  // ln_b
        (float*)d_out);
}